// round 4
// baseline (speedup 1.0000x reference)
#include <cuda_runtime.h>

#define N_NODES   1000000
#define DIM       128
#define B_GRAPHS  2048

// Scratch (no cudaMalloc allowed): transposed W for coalesced GEMM reads
__device__ float g_Wt[DIM * DIM];

// ---------------------------------------------------------------------------
// Kernel 0: transpose W (64KB).  g_Wt[k*DIM + j] = W[j*DIM + k]
// ---------------------------------------------------------------------------
__global__ void transpose_W_kernel(const float* __restrict__ W) {
    int i = blockIdx.x * blockDim.x + threadIdx.x;
    if (i < DIM * DIM) {
        int j = i >> 7;
        int k = i & (DIM - 1);
        g_Wt[k * DIM + j] = W[i];
    }
}

// ---------------------------------------------------------------------------
// Fused kernel: one block per graph (seg ids are SORTED -> contiguous range).
//   1) binary-search [start, end) of graph g
//   2) pass 1: register segment-sum over rows (no atomics, no pool buffer)
//   3) smem GEMM row: vn = vn_h + relu((vn_h + pool) @ W^T + b)
//   4) pass 2 REVERSED: h_out = h + vn  (recently-read rows hit L2)
// blockDim = DIM; thread t owns column t. All row accesses coalesced.
// ---------------------------------------------------------------------------
__global__ void fused_vn_kernel(const float* __restrict__ h,
                                const float* __restrict__ vn_h,
                                const float* __restrict__ b,
                                const int*   __restrict__ seg,
                                float*       __restrict__ vn_out,
                                float*       __restrict__ h_out) {
    __shared__ float sx[DIM];
    __shared__ int   sbounds[2];

    int g = blockIdx.x;
    int t = threadIdx.x;

    // --- bounds via binary search (threads 0,1: lower_bound(g), lower_bound(g+1))
    if (t < 2) {
        int target = g + t;
        int lo = 0, hi = N_NODES;
        while (lo < hi) {
            int mid = (lo + hi) >> 1;
            if (__ldg(&seg[mid]) < target) lo = mid + 1;
            else                           hi = mid;
        }
        sbounds[t] = lo;
    }
    __syncthreads();
    int start = sbounds[0];
    int end   = sbounds[1];

    // --- pass 1: segment sum (streaming, coalesced, MLP via unroll)
    float acc = 0.0f;
    #pragma unroll 8
    for (int r = start; r < end; ++r)
        acc += __ldg(&h[r * DIM + t]);

    // --- VN update: x = vn_h + pool; y = relu(x @ W^T + b); vn = vn_h + y
    float vh = __ldg(&vn_h[g * DIM + t]);
    sx[t] = vh + acc;
    __syncthreads();

    float acc2 = 0.0f;
    #pragma unroll 8
    for (int k = 0; k < DIM; ++k)
        acc2 = fmaf(sx[k], __ldg(&g_Wt[k * DIM + t]), acc2);   // smem bcast + coalesced L2

    float vn = vh + fmaxf(acc2 + __ldg(&b[t]), 0.0f);
    vn_out[g * DIM + t] = vn;

    // --- pass 2 (reverse order for L2 reuse of pass-1 lines): h_out = h + vn
    #pragma unroll 4
    for (int r = end - 1; r >= start; --r)
        h_out[r * DIM + t] = __ldg(&h[r * DIM + t]) + vn;
}

// ---------------------------------------------------------------------------
// Launch: out = [vn_out (B*DIM floats) | h_out (N*DIM floats)]
// ---------------------------------------------------------------------------
extern "C" void kernel_launch(void* const* d_in, const int* in_sizes, int n_in,
                              void* d_out, int out_size) {
    const float* h    = (const float*)d_in[0];
    const float* vn_h = (const float*)d_in[1];
    const float* W    = (const float*)d_in[2];
    const float* b    = (const float*)d_in[3];
    const int*   seg  = (const int*)  d_in[4];

    float* out    = (float*)d_out;
    float* vn_out = out;                       // [B, DIM]
    float* h_out  = out + B_GRAPHS * DIM;      // [N, DIM]

    transpose_W_kernel<<<(DIM * DIM + 255) / 256, 256>>>(W);
    fused_vn_kernel<<<B_GRAPHS, DIM>>>(h, vn_h, b, seg, vn_out, h_out);
}

// round 5
// speedup vs baseline: 1.0159x; 1.0159x over previous
#include <cuda_runtime.h>

#define N_NODES   1000000
#define DIM       128
#define B_GRAPHS  2048

// Scratch (no cudaMalloc allowed): transposed W for coalesced GEMM reads
__device__ float g_Wt[DIM * DIM];

// ---------------------------------------------------------------------------
// Kernel 0: transpose W (64KB).  g_Wt[k*DIM + j] = W[j*DIM + k]
// ---------------------------------------------------------------------------
__global__ void transpose_W_kernel(const float* __restrict__ W) {
    int i = blockIdx.x * blockDim.x + threadIdx.x;
    if (i < DIM * DIM) {
        int j = i >> 7;
        int k = i & (DIM - 1);
        g_Wt[k * DIM + j] = W[i];
    }
}

// ---------------------------------------------------------------------------
// Fused kernel: one block per graph (seg ids are SORTED -> contiguous range).
//   1) binary-search [start, end) of graph g
//   2) pass 1: register segment-sum over rows (no atomics, no pool buffer)
//   3) smem GEMM row: vn = vn_h + relu((vn_h + pool) @ W^T + b)
//   4) pass 2 REVERSED: h_out = h + vn  (recently-read rows hit L2)
// blockDim = DIM; thread t owns column t. All row accesses coalesced.
// ---------------------------------------------------------------------------
__global__ void fused_vn_kernel(const float* __restrict__ h,
                                const float* __restrict__ vn_h,
                                const float* __restrict__ b,
                                const int*   __restrict__ seg,
                                float*       __restrict__ vn_out,
                                float*       __restrict__ h_out) {
    __shared__ float sx[DIM];
    __shared__ int   sbounds[2];

    int g = blockIdx.x;
    int t = threadIdx.x;

    // --- bounds via binary search (threads 0,1: lower_bound(g), lower_bound(g+1))
    if (t < 2) {
        int target = g + t;
        int lo = 0, hi = N_NODES;
        while (lo < hi) {
            int mid = (lo + hi) >> 1;
            if (__ldg(&seg[mid]) < target) lo = mid + 1;
            else                           hi = mid;
        }
        sbounds[t] = lo;
    }
    __syncthreads();
    int start = sbounds[0];
    int end   = sbounds[1];

    // --- pass 1: segment sum (streaming, coalesced, MLP via unroll)
    float acc = 0.0f;
    #pragma unroll 8
    for (int r = start; r < end; ++r)
        acc += __ldg(&h[r * DIM + t]);

    // --- VN update: x = vn_h + pool; y = relu(x @ W^T + b); vn = vn_h + y
    float vh = __ldg(&vn_h[g * DIM + t]);
    sx[t] = vh + acc;
    __syncthreads();

    float acc2 = 0.0f;
    #pragma unroll 8
    for (int k = 0; k < DIM; ++k)
        acc2 = fmaf(sx[k], __ldg(&g_Wt[k * DIM + t]), acc2);   // smem bcast + coalesced L2

    float vn = vh + fmaxf(acc2 + __ldg(&b[t]), 0.0f);
    vn_out[g * DIM + t] = vn;

    // --- pass 2 (reverse order for L2 reuse of pass-1 lines): h_out = h + vn
    #pragma unroll 4
    for (int r = end - 1; r >= start; --r)
        h_out[r * DIM + t] = __ldg(&h[r * DIM + t]) + vn;
}

// ---------------------------------------------------------------------------
// Launch: out = [vn_out (B*DIM floats) | h_out (N*DIM floats)]
// ---------------------------------------------------------------------------
extern "C" void kernel_launch(void* const* d_in, const int* in_sizes, int n_in,
                              void* d_out, int out_size) {
    const float* h    = (const float*)d_in[0];
    const float* vn_h = (const float*)d_in[1];
    const float* W    = (const float*)d_in[2];
    const float* b    = (const float*)d_in[3];
    const int*   seg  = (const int*)  d_in[4];

    float* out    = (float*)d_out;
    float* vn_out = out;                       // [B, DIM]
    float* h_out  = out + B_GRAPHS * DIM;      // [N, DIM]

    transpose_W_kernel<<<(DIM * DIM + 255) / 256, 256>>>(W);
    fused_vn_kernel<<<B_GRAPHS, DIM>>>(h, vn_h, b, seg, vn_out, h_out);
}

// round 6
// speedup vs baseline: 1.0195x; 1.0036x over previous
#include <cuda_runtime.h>

#define N_NODES   1000000
#define DIM       128
#define B_GRAPHS  2048

// Scratch (no cudaMalloc allowed): transposed W for coalesced GEMM reads
__device__ float g_Wt[DIM * DIM];

// ---------------------------------------------------------------------------
// Kernel 0: transpose W (64KB).  g_Wt[k*DIM + j] = W[j*DIM + k]
// ---------------------------------------------------------------------------
__global__ void transpose_W_kernel(const float* __restrict__ W) {
    int i = blockIdx.x * blockDim.x + threadIdx.x;
    if (i < DIM * DIM) {
        int j = i >> 7;
        int k = i & (DIM - 1);
        g_Wt[k * DIM + j] = W[i];
    }
}

// ---------------------------------------------------------------------------
// Fused kernel: one block per graph (seg ids are SORTED -> contiguous range).
//   1) binary-search [start, end) of graph g
//   2) pass 1: register segment-sum over rows (no atomics, no pool buffer)
//   3) smem GEMM row: vn = vn_h + relu((vn_h + pool) @ W^T + b)
//   4) pass 2 REVERSED: h_out = h + vn  (recently-read rows hit L2)
// blockDim = DIM; thread t owns column t. All row accesses coalesced.
// ---------------------------------------------------------------------------
__global__ void fused_vn_kernel(const float* __restrict__ h,
                                const float* __restrict__ vn_h,
                                const float* __restrict__ b,
                                const int*   __restrict__ seg,
                                float*       __restrict__ vn_out,
                                float*       __restrict__ h_out) {
    __shared__ float sx[DIM];
    __shared__ int   sbounds[2];

    int g = blockIdx.x;
    int t = threadIdx.x;

    // --- bounds via binary search (threads 0,1: lower_bound(g), lower_bound(g+1))
    if (t < 2) {
        int target = g + t;
        int lo = 0, hi = N_NODES;
        while (lo < hi) {
            int mid = (lo + hi) >> 1;
            if (__ldg(&seg[mid]) < target) lo = mid + 1;
            else                           hi = mid;
        }
        sbounds[t] = lo;
    }
    __syncthreads();
    int start = sbounds[0];
    int end   = sbounds[1];

    // --- pass 1: segment sum (streaming, coalesced, MLP via unroll)
    float acc = 0.0f;
    #pragma unroll 8
    for (int r = start; r < end; ++r)
        acc += __ldg(&h[r * DIM + t]);

    // --- VN update: x = vn_h + pool; y = relu(x @ W^T + b); vn = vn_h + y
    float vh = __ldg(&vn_h[g * DIM + t]);
    sx[t] = vh + acc;
    __syncthreads();

    float acc2 = 0.0f;
    #pragma unroll 8
    for (int k = 0; k < DIM; ++k)
        acc2 = fmaf(sx[k], __ldg(&g_Wt[k * DIM + t]), acc2);   // smem bcast + coalesced L2

    float vn = vh + fmaxf(acc2 + __ldg(&b[t]), 0.0f);
    vn_out[g * DIM + t] = vn;

    // --- pass 2 (reverse order for L2 reuse of pass-1 lines): h_out = h + vn
    #pragma unroll 4
    for (int r = end - 1; r >= start; --r)
        h_out[r * DIM + t] = __ldg(&h[r * DIM + t]) + vn;
}

// ---------------------------------------------------------------------------
// Launch: out = [vn_out (B*DIM floats) | h_out (N*DIM floats)]
// ---------------------------------------------------------------------------
extern "C" void kernel_launch(void* const* d_in, const int* in_sizes, int n_in,
                              void* d_out, int out_size) {
    const float* h    = (const float*)d_in[0];
    const float* vn_h = (const float*)d_in[1];
    const float* W    = (const float*)d_in[2];
    const float* b    = (const float*)d_in[3];
    const int*   seg  = (const int*)  d_in[4];

    float* out    = (float*)d_out;
    float* vn_out = out;                       // [B, DIM]
    float* h_out  = out + B_GRAPHS * DIM;      // [N, DIM]

    transpose_W_kernel<<<(DIM * DIM + 255) / 256, 256>>>(W);
    fused_vn_kernel<<<B_GRAPHS, DIM>>>(h, vn_h, b, seg, vn_out, h_out);
}